// round 14
// baseline (speedup 1.0000x reference)
#include <cuda_runtime.h>
#include <cuda_bf16.h>
#include <cuda_fp16.h>
#include <math.h>
#include <stdint.h>

#define B_    4
#define N_    4096
#define DIN_  512
#define DOUT_ 128
#define MAXDEG 128
#define NEG_BIG -1e30f

// ---------------- scratch (static device memory; no allocs) ----------------
__device__ __half g_whh[B_ * N_ * DOUT_];   // x @ W (fp16)   4 MB
__device__ __half g_outh[B_ * N_ * DOUT_];  // att @ wh       4 MB
__device__ float g_sT[N_ * 4];              // s transposed [i][b]
__device__ float g_dT[N_ * 4];              // d transposed [i][b]
__device__ float g_sumwh[B_ * DOUT_];       // per-graph colsum (deg==0 fallback)
__device__ int   g_cols[N_ * MAXDEG];
__device__ int   g_deg[N_];
__device__ int   g_flag[N_ * 2];            // out-ready flags [row][pair]
__device__ uint32_t g_Wh[DIN_ * DOUT_ / 2]; // W as fp16x2 packed (128 KB)

// ============================ helpers =======================================
__device__ __forceinline__ uint32_t smem_u32(const void* p) {
    uint32_t a;
    asm("{ .reg .u64 t; cvta.to.shared.u64 t, %1; cvt.u32.u64 %0, t; }" : "=r"(a) : "l"(p));
    return a;
}
__device__ __forceinline__ void ldm_x4(uint32_t* f, uint32_t addr) {
    asm volatile("ldmatrix.sync.aligned.m8n8.x4.shared.b16 {%0,%1,%2,%3}, [%4];"
                 : "=r"(f[0]), "=r"(f[1]), "=r"(f[2]), "=r"(f[3]) : "r"(addr));
}
__device__ __forceinline__ void ldm_x4t(uint32_t* f, uint32_t addr) {
    asm volatile("ldmatrix.sync.aligned.m8n8.x4.trans.shared.b16 {%0,%1,%2,%3}, [%4];"
                 : "=r"(f[0]), "=r"(f[1]), "=r"(f[2]), "=r"(f[3]) : "r"(addr));
}
__device__ __forceinline__ void mma_f16(float* c, const uint32_t* a, const uint32_t* b) {
    asm volatile(
        "mma.sync.aligned.m16n8k16.row.col.f32.f16.f16.f32 "
        "{%0,%1,%2,%3}, {%4,%5,%6,%7}, {%8,%9}, {%0,%1,%2,%3};"
        : "+f"(c[0]), "+f"(c[1]), "+f"(c[2]), "+f"(c[3])
        : "r"(a[0]), "r"(a[1]), "r"(a[2]), "r"(a[3]), "r"(b[0]), "r"(b[1]));
}
__device__ __forceinline__ uint32_t pack_half(float x, float y) {
    __half2 h = __floats2half2_rn(x, y);
    return *(uint32_t*)&h;
}

// =============== W -> fp16 + zero g_sumwh/g_flag ===========================
__global__ __launch_bounds__(256) void convw_kernel(const float* __restrict__ W) {
    int gidx = blockIdx.x * 256 + threadIdx.x;
    if (gidx < N_ * 2) g_flag[gidx] = 0;
    if (gidx < B_ * DOUT_) g_sumwh[gidx] = 0.0f;
    float4 v = ((const float4*)W)[gidx];
    g_Wh[gidx * 2]     = pack_half(v.x, v.y);
    g_Wh[gidx * 2 + 1] = pack_half(v.z, v.w);
}

// =============== CSR build: warp/row, 4 loads in flight ====================
__global__ void csr_build_kernel(const float* __restrict__ adj) {
    int warp = (blockIdx.x * blockDim.x + threadIdx.x) >> 5;
    int lane = threadIdx.x & 31;
    if (warp >= N_) return;
    const float4* row = (const float4*)(adj + (size_t)warp * N_);
    int cnt = 0;
    for (int base = 0; base < N_; base += 512) {
        float4 v0 = row[(base >> 2) + lane];
        float4 v1 = row[(base >> 2) + 32 + lane];
        float4 v2 = row[(base >> 2) + 64 + lane];
        float4 v3 = row[(base >> 2) + 96 + lane];
        float c16[16] = {v0.x, v0.y, v0.z, v0.w, v1.x, v1.y, v1.z, v1.w,
                         v2.x, v2.y, v2.z, v2.w, v3.x, v3.y, v3.z, v3.w};
#pragma unroll
        for (int h = 0; h < 4; h++) {
#pragma unroll
            for (int c = 0; c < 4; c++) {
                float f = c16[h * 4 + c];
                unsigned m = __ballot_sync(0xffffffffu, f > 0.0f);
                if (f > 0.0f) {
                    int pos = cnt + __popc(m & ((1u << lane) - 1u));
                    if (pos < MAXDEG)
                        g_cols[warp * MAXDEG + pos] = base + h * 128 + lane * 4 + c;
                }
                cnt += __popc(m);
            }
        }
    }
    if (lane == 0) g_deg[warp] = cnt < MAXDEG ? cnt : MAXDEG;
}

// ===== HMMA GEMM (fp16): wh = x @ W.  M-tile 64 -> 256 CTAs, 2/SM ==========
#define KC 32
#define NCH (DIN_ / KC)          // 16
#define A_STG 8192               // 64 rows * 128B
#define B_STG 8192               // 32 k * 128 n * 2B
#define SM_A 0
#define SM_B (2 * A_STG)
#define SM_SD (SM_B + 2 * B_STG)          // s_sm[64], d_sm[64]
#define SM_AV (SM_SD + 512)               // a_s[128], a_d[128]
#define SM_CS (SM_AV + 1024)              // cs[128]
#define SMEM_TOTAL (SM_CS + 512)

__device__ __forceinline__ uint32_t a_off(int r, int gran) {
    return (uint32_t)(r * 128 + ((gran ^ (r & 7)) << 4));
}
__device__ __forceinline__ uint32_t b_off2(int k, int gran) {
    return (uint32_t)(k * 256 + ((gran ^ (k & 7)) << 4));
}

__global__ __launch_bounds__(256, 2) void gemm_hmma_kernel(
    const float* __restrict__ x, const float* __restrict__ a) {
    extern __shared__ char smem[];
    const uint32_t sb = smem_u32(smem);
    const int tid = threadIdx.x;
    const int wid = tid >> 5, lane = tid & 31;
    const int wm = wid >> 1, wn = wid & 1;     // warp tile: 16 rows x 64 cols
    const int tig = lane & 3, grp = lane >> 2;

    float* s_sm = (float*)(smem + SM_SD);
    float* d_sm = (float*)(smem + SM_SD + 256);
    float* a_s  = (float*)(smem + SM_AV);
    float* a_d  = (float*)(smem + SM_AV + 512);
    float* cs   = (float*)(smem + SM_CS);
    if (tid < 128) {
        cs[tid] = 0.0f;
        a_s[tid] = a[tid]; a_d[tid] = a[DOUT_ + tid];
    }
    if (tid < 64) { s_sm[tid] = 0.0f; d_sm[tid] = 0.0f; }

    const int R0 = blockIdx.x * 64;
    const int arow = tid >> 2, akoff = (tid & 3) * 8;
    const float* pA = x + (size_t)(R0 + arow) * DIN_ + akoff;
    const int bk = tid >> 3, bgr = (tid & 7) * 2;
    const uint4* Wh4 = (const uint4*)g_Wh;

    float acc[8][4];
#pragma unroll
    for (int j = 0; j < 8; j++)
#pragma unroll
        for (int q = 0; q < 4; q++) acc[j][q] = 0.0f;

    float4 ra[2];
    uint4 rbh[2];
    ra[0] = *(const float4*)(pA);
    ra[1] = *(const float4*)(pA + 4);
    {
        int gi = bk * 16 + bgr;
        rbh[0] = Wh4[gi];  rbh[1] = Wh4[gi + 1];
    }

    for (int c = 0; c < NCH; c++) {
        const int buf = c & 1;
        char* Abuf = smem + SM_A + buf * A_STG;
        char* Bbuf = smem + SM_B + buf * B_STG;

        {
            const float* fa = (const float*)ra;
#pragma unroll
            for (int p = 0; p < 4; p++) {
                uint32_t hv = pack_half(fa[2 * p], fa[2 * p + 1]);
                int kl = akoff + 2 * p;
                int gr = kl >> 3, wi = (kl & 7) * 2;
                *(uint32_t*)(Abuf + a_off(arow, gr) + wi) = hv;
            }
            *(uint4*)(Bbuf + b_off2(bk, bgr))     = rbh[0];
            *(uint4*)(Bbuf + b_off2(bk, bgr + 1)) = rbh[1];
        }
        __syncthreads();

        if (c + 1 < NCH) {
            const float* qA = pA + (c + 1) * KC;
            ra[0] = *(const float4*)(qA);
            ra[1] = *(const float4*)(qA + 4);
            int gi = (c + 1) * 512 + bk * 16 + bgr;
            rbh[0] = Wh4[gi];  rbh[1] = Wh4[gi + 1];
        }

        const uint32_t Abase = sb + SM_A + buf * A_STG;
        const uint32_t Bbase = sb + SM_B + buf * B_STG;
#pragma unroll
        for (int ks = 0; ks < 2; ks++) {
            uint32_t ahi[4];
            {
                int R = wm * 16 + (lane & 15);
                int gh = 2 * ks + (lane >> 4);
                ldm_x4(ahi, Abase + a_off(R, gh));
            }
            int kk = 16 * ks + (lane & 15);
#pragma unroll
            for (int ntp = 0; ntp < 4; ntp++) {
                int gn = wn * 8 + ntp * 2 + (lane >> 4);
                uint32_t bb[4];
                ldm_x4t(bb, Bbase + b_off2(kk, gn));
                mma_f16(acc[ntp * 2],     ahi, bb);
                mma_f16(acc[ntp * 2 + 1], ahi, bb + 2);
            }
        }
        __syncthreads();
    }

    // ---- epilogue: store wh (fp16), fused s/d dots + column sums ----
    float sacc[2] = {0, 0}, dacc[2] = {0, 0};
    int rbase = R0 + wm * 16 + grp;
#pragma unroll
    for (int nt = 0; nt < 8; nt++) {
        int col = wn * 64 + nt * 8 + tig * 2;
        float* cf = acc[nt];
        sacc[0] += cf[0] * a_s[col] + cf[1] * a_s[col + 1];
        sacc[1] += cf[2] * a_s[col] + cf[3] * a_s[col + 1];
        dacc[0] += cf[0] * a_d[col] + cf[1] * a_d[col + 1];
        dacc[1] += cf[2] * a_d[col] + cf[3] * a_d[col + 1];
        *(__half2*)&g_whh[(size_t)rbase * DOUT_ + col] =
            __float22half2_rn(make_float2(cf[0], cf[1]));
        *(__half2*)&g_whh[(size_t)(rbase + 8) * DOUT_ + col] =
            __float22half2_rn(make_float2(cf[2], cf[3]));

        float v0 = cf[0] + cf[2];
        float v1 = cf[1] + cf[3];
#pragma unroll
        for (int off = 16; off >= 4; off >>= 1) {
            v0 += __shfl_down_sync(0xffffffffu, v0, off);
            v1 += __shfl_down_sync(0xffffffffu, v1, off);
        }
        if (lane < 4) {
            atomicAdd(&cs[col], v0);
            atomicAdd(&cs[col + 1], v1);
        }
    }
#pragma unroll
    for (int h = 0; h < 2; h++) {
        sacc[h] += __shfl_xor_sync(0xffffffffu, sacc[h], 1);
        sacc[h] += __shfl_xor_sync(0xffffffffu, sacc[h], 2);
        dacc[h] += __shfl_xor_sync(0xffffffffu, dacc[h], 1);
        dacc[h] += __shfl_xor_sync(0xffffffffu, dacc[h], 2);
    }
    if (tig == 0) {
        int r = wm * 16 + grp;
        atomicAdd(&s_sm[r], sacc[0]);
        atomicAdd(&s_sm[r + 8], sacc[1]);
        atomicAdd(&d_sm[r], dacc[0]);
        atomicAdd(&d_sm[r + 8], dacc[1]);
    }
    __syncthreads();
    if (tid < 64) {
        int b = R0 / N_;
        int il = (R0 % N_) + tid;
        g_sT[il * 4 + b] = s_sm[tid];
        g_dT[il * 4 + b] = d_sm[tid];
    }
    if (tid < 128) {
        int b = R0 / N_;
        atomicAdd(&g_sumwh[b * DOUT_ + tid], cs[tid]);
    }
}

// ==== FUSED attn + final: persistent, flag-pipelined ========================
// grid 512 x 256 threads, __launch_bounds__(256,4) -> all CTAs resident in
// one wave (592 slots on 148 SMs), so flag spins cannot deadlock.
#define FUSE_GRID 512
#define NUNITS (N_ / 4)   // 1024 units of 4 rows

__global__ __launch_bounds__(256, 4) void attn_final_kernel(float* __restrict__ y) {
    __shared__ float sh_e[8][MAXDEG][2];
    __shared__ int   sh_j[8][MAXDEG];
    const int lane = threadIdx.x & 31;
    const int w = threadIdx.x >> 5;
    const int rl = w >> 1, pr = w & 1;
    const int b0 = 2 * pr;

    // ---------------- phase 1: attention (R12 body) ----------------
    for (int u = blockIdx.x; u < NUNITS; u += FUSE_GRID) {
        int i = u * 4 + rl;
        int deg = g_deg[i];

        if (deg == 0) {
            float inv = 1.0f / (float)N_;
#pragma unroll
            for (int q = 0; q < 2; q++) {
                int b = b0 + q;
                float4 m = ((const float4*)&g_sumwh[b * DOUT_])[lane];
                uint2 o;
                o.x = pack_half(m.x * inv, m.y * inv);
                o.y = pack_half(m.z * inv, m.w * inv);
                ((uint2*)&g_outh[((size_t)b * N_ + i) * DOUT_])[lane] = o;
            }
        } else {
            float2 s2 = *(const float2*)&g_sT[i * 4 + b0];
            float mx0 = NEG_BIG, mx1 = NEG_BIG;
            for (int t = lane; t < deg; t += 32) {
                int j = g_cols[i * MAXDEG + t];
                sh_j[w][t] = j;
                float2 d2 = *(const float2*)&g_dT[j * 4 + b0];
                float e0 = s2.x + d2.x; e0 = e0 > 0.f ? e0 : 0.01f * e0;
                float e1 = s2.y + d2.y; e1 = e1 > 0.f ? e1 : 0.01f * e1;
                *(float2*)sh_e[w][t] = make_float2(e0, e1);
                mx0 = fmaxf(mx0, e0); mx1 = fmaxf(mx1, e1);
            }
#pragma unroll
            for (int off = 16; off > 0; off >>= 1) {
                mx0 = fmaxf(mx0, __shfl_xor_sync(0xffffffffu, mx0, off));
                mx1 = fmaxf(mx1, __shfl_xor_sync(0xffffffffu, mx1, off));
            }
            __syncwarp();
            float se0 = 0.f, se1 = 0.f;
            for (int t = lane; t < deg; t += 32) {
                float2 e = *(float2*)sh_e[w][t];
                float p0 = __expf(e.x - mx0), p1 = __expf(e.y - mx1);
                *(float2*)sh_e[w][t] = make_float2(p0, p1);
                se0 += p0; se1 += p1;
            }
#pragma unroll
            for (int off = 16; off > 0; off >>= 1) {
                se0 += __shfl_xor_sync(0xffffffffu, se0, off);
                se1 += __shfl_xor_sync(0xffffffffu, se1, off);
            }
            float iv0 = 1.f / se0, iv1 = 1.f / se1;
            __syncwarp();

            const uint2* whA = (const uint2*)g_whh + (size_t)b0 * N_ * 32;
            const uint2* whB = whA + (size_t)N_ * 32;
            float aA0 = 0.f, aA1 = 0.f, aA2 = 0.f, aA3 = 0.f;
            float aB0 = 0.f, aB1 = 0.f, aB2 = 0.f, aB3 = 0.f;

            int k = 0;
            for (; k + 4 <= deg; k += 4) {
                uint2 vA[4], vB[4];
                float pA[4], pB[4];
#pragma unroll
                for (int uu = 0; uu < 4; uu++) {
                    size_t o = (size_t)sh_j[w][k + uu] * 32 + lane;
                    vA[uu] = whA[o]; vB[uu] = whB[o];
                    float2 p = *(float2*)sh_e[w][k + uu];
                    pA[uu] = p.x * iv0; pB[uu] = p.y * iv1;
                }
#pragma unroll
                for (int uu = 0; uu < 4; uu++) {
                    float2 f;
                    f = __half22float2(*(__half2*)&vA[uu].x); aA0 += pA[uu] * f.x; aA1 += pA[uu] * f.y;
                    f = __half22float2(*(__half2*)&vA[uu].y); aA2 += pA[uu] * f.x; aA3 += pA[uu] * f.y;
                    f = __half22float2(*(__half2*)&vB[uu].x); aB0 += pB[uu] * f.x; aB1 += pB[uu] * f.y;
                    f = __half22float2(*(__half2*)&vB[uu].y); aB2 += pB[uu] * f.x; aB3 += pB[uu] * f.y;
                }
            }
            for (; k < deg; k++) {
                size_t o0 = (size_t)sh_j[w][k] * 32 + lane;
                uint2 vA0 = whA[o0], vB0 = whB[o0];
                float2 p0 = *(float2*)sh_e[w][k];
                float pA0 = p0.x * iv0, pB0 = p0.y * iv1;
                float2 f;
                f = __half22float2(*(__half2*)&vA0.x); aA0 += pA0 * f.x; aA1 += pA0 * f.y;
                f = __half22float2(*(__half2*)&vA0.y); aA2 += pA0 * f.x; aA3 += pA0 * f.y;
                f = __half22float2(*(__half2*)&vB0.x); aB0 += pB0 * f.x; aB1 += pB0 * f.y;
                f = __half22float2(*(__half2*)&vB0.y); aB2 += pB0 * f.x; aB3 += pB0 * f.y;
            }
            uint2 oA, oB;
            oA.x = pack_half(aA0, aA1); oA.y = pack_half(aA2, aA3);
            oB.x = pack_half(aB0, aB1); oB.y = pack_half(aB2, aB3);
            ((uint2*)&g_outh[((size_t)b0 * N_ + i) * DOUT_])[lane] = oA;
            ((uint2*)&g_outh[((size_t)(b0 + 1) * N_ + i) * DOUT_])[lane] = oB;
        }
        // publish: out rows for (i, pr) are ready
        __threadfence();
        if (lane == 0) g_flag[i * 2 + pr] = 1;
    }

    // ---------------- phase 2: final = relu(adj @ out) ----------------
    for (int u = blockIdx.x; u < NUNITS; u += FUSE_GRID) {
        int i = u * 4 + rl;
        int deg = g_deg[i];

        const uint2* ouA = (const uint2*)g_outh + (size_t)b0 * N_ * 32;
        const uint2* ouB = ouA + (size_t)N_ * 32;
        float aA0 = 0.f, aA1 = 0.f, aA2 = 0.f, aA3 = 0.f;
        float aB0 = 0.f, aB1 = 0.f, aB2 = 0.f, aB3 = 0.f;

        if (deg <= 32) {
            int jreg = lane < deg ? g_cols[i * MAXDEG + lane] : 0;
            // spin until all neighbors' out rows are published
            unsigned ok = (lane >= deg) ? 1u : 0u;
            while (__ballot_sync(0xffffffffu, ok) != 0xffffffffu) {
                if (!ok) ok = ((volatile int*)g_flag)[jreg * 2 + pr] != 0;
                if (!ok) __nanosleep(64);
            }
            __threadfence();

            int k = 0;
            for (; k + 4 <= deg; k += 4) {
                int jk[4];
#pragma unroll
                for (int uu = 0; uu < 4; uu++)
                    jk[uu] = __shfl_sync(0xffffffffu, jreg, k + uu);
                uint2 vA[4], vB[4];
#pragma unroll
                for (int uu = 0; uu < 4; uu++) {
                    size_t o = (size_t)jk[uu] * 32 + lane;
                    vA[uu] = ouA[o]; vB[uu] = ouB[o];
                }
#pragma unroll
                for (int uu = 0; uu < 4; uu++) {
                    float2 f;
                    f = __half22float2(*(__half2*)&vA[uu].x); aA0 += f.x; aA1 += f.y;
                    f = __half22float2(*(__half2*)&vA[uu].y); aA2 += f.x; aA3 += f.y;
                    f = __half22float2(*(__half2*)&vB[uu].x); aB0 += f.x; aB1 += f.y;
                    f = __half22float2(*(__half2*)&vB[uu].y); aB2 += f.x; aB3 += f.y;
                }
            }
            for (; k < deg; k++) {
                int jk = __shfl_sync(0xffffffffu, jreg, k);
                size_t o0 = (size_t)jk * 32 + lane;
                uint2 vA0 = ouA[o0], vB0 = ouB[o0];
                float2 f;
                f = __half22float2(*(__half2*)&vA0.x); aA0 += f.x; aA1 += f.y;
                f = __half22float2(*(__half2*)&vA0.y); aA2 += f.x; aA3 += f.y;
                f = __half22float2(*(__half2*)&vB0.x); aB0 += f.x; aB1 += f.y;
                f = __half22float2(*(__half2*)&vB0.y); aB2 += f.x; aB3 += f.y;
            }
        } else {
            // rare fallback: reload cols, per-element spin
            for (int t = lane; t < deg; t += 32) {
                int j = g_cols[i * MAXDEG + t];
                sh_j[w][t] = j;
                while (((volatile int*)g_flag)[j * 2 + pr] == 0) __nanosleep(64);
            }
            __syncwarp();
            __threadfence();
            for (int k = 0; k < deg; k++) {
                size_t o0 = (size_t)sh_j[w][k] * 32 + lane;
                uint2 vA0 = ouA[o0], vB0 = ouB[o0];
                float2 f;
                f = __half22float2(*(__half2*)&vA0.x); aA0 += f.x; aA1 += f.y;
                f = __half22float2(*(__half2*)&vA0.y); aA2 += f.x; aA3 += f.y;
                f = __half22float2(*(__half2*)&vB0.x); aB0 += f.x; aB1 += f.y;
                f = __half22float2(*(__half2*)&vB0.y); aB2 += f.x; aB3 += f.y;
            }
        }
        float4 rA = make_float4(fmaxf(aA0, 0.f), fmaxf(aA1, 0.f),
                                fmaxf(aA2, 0.f), fmaxf(aA3, 0.f));
        float4 rB = make_float4(fmaxf(aB0, 0.f), fmaxf(aB1, 0.f),
                                fmaxf(aB2, 0.f), fmaxf(aB3, 0.f));
        ((float4*)&y[((size_t)b0 * N_ + i) * DOUT_])[lane] = rA;
        ((float4*)&y[((size_t)(b0 + 1) * N_ + i) * DOUT_])[lane] = rB;
    }
}

// ---------------- launch ----------------
extern "C" void kernel_launch(void* const* d_in, const int* in_sizes, int n_in,
                              void* d_out, int out_size) {
    const float* x   = (const float*)d_in[0];  // (B, N, DIN)
    const float* adj = (const float*)d_in[1];  // (N, N)
    const float* wts = (const float*)d_in[2];  // (DIN, DOUT)
    const float* a   = (const float*)d_in[3];  // (2*DOUT, 1)
    float* y = (float*)d_out;

    static cudaStream_t s2;
    static cudaEvent_t evA, evC;
    static int inited = 0;
    if (!inited) {
        cudaFuncSetAttribute(gemm_hmma_kernel,
                             cudaFuncAttributeMaxDynamicSharedMemorySize, SMEM_TOTAL);
        cudaStreamCreateWithFlags(&s2, cudaStreamNonBlocking);
        cudaEventCreateWithFlags(&evA, cudaEventDisableTiming);
        cudaEventCreateWithFlags(&evC, cudaEventDisableTiming);
        inited = 1;
    }
    cudaStream_t s0 = 0;

    // fork: csr on s2 overlaps convW+GEMM on s0; join before fused kernel
    cudaEventRecord(evA, s0);
    cudaStreamWaitEvent(s2, evA, 0);
    csr_build_kernel<<<N_ / 8, 256, 0, s2>>>(adj);
    cudaEventRecord(evC, s2);

    convw_kernel<<<DIN_ * DOUT_ / 1024, 256, 0, s0>>>(wts);
    gemm_hmma_kernel<<<(B_ * N_) / 64, 256, SMEM_TOTAL, s0>>>(x, a);
    cudaStreamWaitEvent(s0, evC, 0);

    attn_final_kernel<<<FUSE_GRID, 256, 0, s0>>>(y);
}

// round 15
// speedup vs baseline: 1.0397x; 1.0397x over previous
#include <cuda_runtime.h>
#include <cuda_bf16.h>
#include <cuda_fp16.h>
#include <math.h>
#include <stdint.h>

#define B_    4
#define N_    4096
#define DIN_  512
#define DOUT_ 128
#define MAXDEG 128
#define NEG_BIG -1e30f

// ---------------- scratch (static device memory; no allocs) ----------------
__device__ __half g_whh[B_ * N_ * DOUT_];   // x @ W (fp16)   4 MB
__device__ __half g_outh[B_ * N_ * DOUT_];  // att @ wh       4 MB
__device__ float g_sT[N_ * 4];              // s transposed [i][b]
__device__ float g_dT[N_ * 4];              // d transposed [i][b]
__device__ float g_sumwh[B_ * DOUT_];       // per-graph colsum (deg==0 fallback)
__device__ int   g_cols[N_ * MAXDEG];
__device__ int   g_deg[N_];
__device__ uint32_t g_Wh[DIN_ * DOUT_ / 2]; // W as fp16x2 packed (128 KB)

// ============================ helpers =======================================
__device__ __forceinline__ uint32_t smem_u32(const void* p) {
    uint32_t a;
    asm("{ .reg .u64 t; cvta.to.shared.u64 t, %1; cvt.u32.u64 %0, t; }" : "=r"(a) : "l"(p));
    return a;
}
__device__ __forceinline__ void ldm_x4(uint32_t* f, uint32_t addr) {
    asm volatile("ldmatrix.sync.aligned.m8n8.x4.shared.b16 {%0,%1,%2,%3}, [%4];"
                 : "=r"(f[0]), "=r"(f[1]), "=r"(f[2]), "=r"(f[3]) : "r"(addr));
}
__device__ __forceinline__ void ldm_x4t(uint32_t* f, uint32_t addr) {
    asm volatile("ldmatrix.sync.aligned.m8n8.x4.trans.shared.b16 {%0,%1,%2,%3}, [%4];"
                 : "=r"(f[0]), "=r"(f[1]), "=r"(f[2]), "=r"(f[3]) : "r"(addr));
}
__device__ __forceinline__ void mma_f16(float* c, const uint32_t* a, const uint32_t* b) {
    asm volatile(
        "mma.sync.aligned.m16n8k16.row.col.f32.f16.f16.f32 "
        "{%0,%1,%2,%3}, {%4,%5,%6,%7}, {%8,%9}, {%0,%1,%2,%3};"
        : "+f"(c[0]), "+f"(c[1]), "+f"(c[2]), "+f"(c[3])
        : "r"(a[0]), "r"(a[1]), "r"(a[2]), "r"(a[3]), "r"(b[0]), "r"(b[1]));
}
__device__ __forceinline__ uint32_t pack_half(float x, float y) {
    __half2 h = __floats2half2_rn(x, y);
    return *(uint32_t*)&h;
}

// =============== W -> fp16 + zero g_sumwh ==================================
__global__ __launch_bounds__(256) void convw_kernel(const float* __restrict__ W) {
    if (blockIdx.x < 2) g_sumwh[blockIdx.x * 256 + threadIdx.x] = 0.0f;
    int i = blockIdx.x * 256 + threadIdx.x;     // 16384 float4s
    float4 v = ((const float4*)W)[i];
    g_Wh[i * 2]     = pack_half(v.x, v.y);
    g_Wh[i * 2 + 1] = pack_half(v.z, v.w);
}

// =============== CSR build: warp/row, 4 loads in flight ====================
__global__ void csr_build_kernel(const float* __restrict__ adj) {
    int warp = (blockIdx.x * blockDim.x + threadIdx.x) >> 5;
    int lane = threadIdx.x & 31;
    if (warp >= N_) return;
    const float4* row = (const float4*)(adj + (size_t)warp * N_);
    int cnt = 0;
    for (int base = 0; base < N_; base += 512) {
        float4 v0 = row[(base >> 2) + lane];
        float4 v1 = row[(base >> 2) + 32 + lane];
        float4 v2 = row[(base >> 2) + 64 + lane];
        float4 v3 = row[(base >> 2) + 96 + lane];
        float c16[16] = {v0.x, v0.y, v0.z, v0.w, v1.x, v1.y, v1.z, v1.w,
                         v2.x, v2.y, v2.z, v2.w, v3.x, v3.y, v3.z, v3.w};
#pragma unroll
        for (int h = 0; h < 4; h++) {
#pragma unroll
            for (int c = 0; c < 4; c++) {
                float f = c16[h * 4 + c];
                unsigned m = __ballot_sync(0xffffffffu, f > 0.0f);
                if (f > 0.0f) {
                    int pos = cnt + __popc(m & ((1u << lane) - 1u));
                    if (pos < MAXDEG)
                        g_cols[warp * MAXDEG + pos] = base + h * 128 + lane * 4 + c;
                }
                cnt += __popc(m);
            }
        }
    }
    if (lane == 0) g_deg[warp] = cnt < MAXDEG ? cnt : MAXDEG;
}

// ===== HMMA GEMM (fp16): wh = x @ W.  M-tile 64 -> 256 CTAs, 2/SM ==========
#define KC 32
#define NCH (DIN_ / KC)          // 16
#define A_STG 8192               // 64 rows * 128B
#define B_STG 8192               // 32 k * 128 n * 2B
#define SM_A 0
#define SM_B (2 * A_STG)
#define SM_SD (SM_B + 2 * B_STG)          // s_sm[64], d_sm[64]
#define SM_AV (SM_SD + 512)               // a_s[128], a_d[128]
#define SM_CS (SM_AV + 1024)              // cs[128]
#define SMEM_TOTAL (SM_CS + 512)

__device__ __forceinline__ uint32_t a_off(int r, int gran) {
    return (uint32_t)(r * 128 + ((gran ^ (r & 7)) << 4));
}
__device__ __forceinline__ uint32_t b_off2(int k, int gran) {
    return (uint32_t)(k * 256 + ((gran ^ (k & 7)) << 4));
}

__global__ __launch_bounds__(256, 2) void gemm_hmma_kernel(
    const float* __restrict__ x, const float* __restrict__ a) {
    extern __shared__ char smem[];
    const uint32_t sb = smem_u32(smem);
    const int tid = threadIdx.x;
    const int wid = tid >> 5, lane = tid & 31;
    const int wm = wid >> 1, wn = wid & 1;     // warp tile: 16 rows x 64 cols
    const int tig = lane & 3, grp = lane >> 2;

    float* s_sm = (float*)(smem + SM_SD);
    float* d_sm = (float*)(smem + SM_SD + 256);
    float* a_s  = (float*)(smem + SM_AV);
    float* a_d  = (float*)(smem + SM_AV + 512);
    float* cs   = (float*)(smem + SM_CS);
    if (tid < 128) {
        cs[tid] = 0.0f;
        a_s[tid] = a[tid]; a_d[tid] = a[DOUT_ + tid];
    }
    if (tid < 64) { s_sm[tid] = 0.0f; d_sm[tid] = 0.0f; }

    const int R0 = blockIdx.x * 64;
    const int arow = tid >> 2, akoff = (tid & 3) * 8;
    const float* pA = x + (size_t)(R0 + arow) * DIN_ + akoff;
    const int bk = tid >> 3, bgr = (tid & 7) * 2;
    const uint4* Wh4 = (const uint4*)g_Wh;

    float acc[8][4];
#pragma unroll
    for (int j = 0; j < 8; j++)
#pragma unroll
        for (int q = 0; q < 4; q++) acc[j][q] = 0.0f;

    float4 ra[2];
    uint4 rbh[2];
    ra[0] = *(const float4*)(pA);
    ra[1] = *(const float4*)(pA + 4);
    {
        int gi = bk * 16 + bgr;
        rbh[0] = Wh4[gi];  rbh[1] = Wh4[gi + 1];
    }

    for (int c = 0; c < NCH; c++) {
        const int buf = c & 1;
        char* Abuf = smem + SM_A + buf * A_STG;
        char* Bbuf = smem + SM_B + buf * B_STG;

        {
            const float* fa = (const float*)ra;
#pragma unroll
            for (int p = 0; p < 4; p++) {
                uint32_t hv = pack_half(fa[2 * p], fa[2 * p + 1]);
                int kl = akoff + 2 * p;
                int gr = kl >> 3, wi = (kl & 7) * 2;
                *(uint32_t*)(Abuf + a_off(arow, gr) + wi) = hv;
            }
            *(uint4*)(Bbuf + b_off2(bk, bgr))     = rbh[0];
            *(uint4*)(Bbuf + b_off2(bk, bgr + 1)) = rbh[1];
        }
        __syncthreads();

        if (c + 1 < NCH) {
            const float* qA = pA + (c + 1) * KC;
            ra[0] = *(const float4*)(qA);
            ra[1] = *(const float4*)(qA + 4);
            int gi = (c + 1) * 512 + bk * 16 + bgr;
            rbh[0] = Wh4[gi];  rbh[1] = Wh4[gi + 1];
        }

        const uint32_t Abase = sb + SM_A + buf * A_STG;
        const uint32_t Bbase = sb + SM_B + buf * B_STG;
#pragma unroll
        for (int ks = 0; ks < 2; ks++) {
            uint32_t ahi[4];
            {
                int R = wm * 16 + (lane & 15);
                int gh = 2 * ks + (lane >> 4);
                ldm_x4(ahi, Abase + a_off(R, gh));
            }
            int kk = 16 * ks + (lane & 15);
#pragma unroll
            for (int ntp = 0; ntp < 4; ntp++) {
                int gn = wn * 8 + ntp * 2 + (lane >> 4);
                uint32_t bb[4];
                ldm_x4t(bb, Bbase + b_off2(kk, gn));
                mma_f16(acc[ntp * 2],     ahi, bb);
                mma_f16(acc[ntp * 2 + 1], ahi, bb + 2);
            }
        }
        __syncthreads();
    }

    // ---- epilogue: store wh (fp16), fused s/d dots + column sums ----
    float sacc[2] = {0, 0}, dacc[2] = {0, 0};
    int rbase = R0 + wm * 16 + grp;
#pragma unroll
    for (int nt = 0; nt < 8; nt++) {
        int col = wn * 64 + nt * 8 + tig * 2;
        float* cf = acc[nt];
        sacc[0] += cf[0] * a_s[col] + cf[1] * a_s[col + 1];
        sacc[1] += cf[2] * a_s[col] + cf[3] * a_s[col + 1];
        dacc[0] += cf[0] * a_d[col] + cf[1] * a_d[col + 1];
        dacc[1] += cf[2] * a_d[col] + cf[3] * a_d[col + 1];
        *(__half2*)&g_whh[(size_t)rbase * DOUT_ + col] =
            __float22half2_rn(make_float2(cf[0], cf[1]));
        *(__half2*)&g_whh[(size_t)(rbase + 8) * DOUT_ + col] =
            __float22half2_rn(make_float2(cf[2], cf[3]));

        float v0 = cf[0] + cf[2];
        float v1 = cf[1] + cf[3];
#pragma unroll
        for (int off = 16; off >= 4; off >>= 1) {
            v0 += __shfl_down_sync(0xffffffffu, v0, off);
            v1 += __shfl_down_sync(0xffffffffu, v1, off);
        }
        if (lane < 4) {
            atomicAdd(&cs[col], v0);
            atomicAdd(&cs[col + 1], v1);
        }
    }
#pragma unroll
    for (int h = 0; h < 2; h++) {
        sacc[h] += __shfl_xor_sync(0xffffffffu, sacc[h], 1);
        sacc[h] += __shfl_xor_sync(0xffffffffu, sacc[h], 2);
        dacc[h] += __shfl_xor_sync(0xffffffffu, dacc[h], 1);
        dacc[h] += __shfl_xor_sync(0xffffffffu, dacc[h], 2);
    }
    if (tig == 0) {
        int r = wm * 16 + grp;
        atomicAdd(&s_sm[r], sacc[0]);
        atomicAdd(&s_sm[r + 8], sacc[1]);
        atomicAdd(&d_sm[r], dacc[0]);
        atomicAdd(&d_sm[r + 8], dacc[1]);
    }
    __syncthreads();
    if (tid < 64) {
        int b = R0 / N_;
        int il = (R0 % N_) + tid;
        g_sT[il * 4 + b] = s_sm[tid];
        g_dT[il * 4 + b] = d_sm[tid];
    }
    if (tid < 128) {
        int b = R0 / N_;
        atomicAdd(&g_sumwh[b * DOUT_ + tid], cs[tid]);
    }
}

// ==== attention SpMM: warp per (row, single graph) — 16384 warps ===========
__global__ __launch_bounds__(256) void attn_kernel() {
    __shared__ float sh_e[8][MAXDEG];   // fallback only (deg > 32)
    __shared__ int   sh_j[8][MAXDEG];
    int lane = threadIdx.x & 31;
    int w = threadIdx.x >> 5;
    int rl = w >> 2, b = w & 3;         // 2 rows x 4 graphs per block
    int i = blockIdx.x * 2 + rl;
    int deg = g_deg[i];

    if (deg == 0) {
        float inv = 1.0f / (float)N_;
        float4 m = ((const float4*)&g_sumwh[b * DOUT_])[lane];
        uint2 o;
        o.x = pack_half(m.x * inv, m.y * inv);
        o.y = pack_half(m.z * inv, m.w * inv);
        ((uint2*)&g_outh[((size_t)b * N_ + i) * DOUT_])[lane] = o;
        return;
    }

    const uint2* whb = (const uint2*)g_whh + (size_t)b * N_ * 32;
    float a0 = 0.f, a1 = 0.f, a2 = 0.f, a3 = 0.f;
    float si = g_sT[i * 4 + b];

    if (deg <= 32) {
        // register softmax: lane t owns edge t
        int jreg = 0;
        float e = NEG_BIG;
        if (lane < deg) {
            jreg = g_cols[i * MAXDEG + lane];
            e = si + g_dT[jreg * 4 + b];
            e = e > 0.f ? e : 0.01f * e;
        }
        float mx = e;
#pragma unroll
        for (int off = 16; off > 0; off >>= 1)
            mx = fmaxf(mx, __shfl_xor_sync(0xffffffffu, mx, off));
        float p = lane < deg ? __expf(e - mx) : 0.f;
        float se = p;
#pragma unroll
        for (int off = 16; off > 0; off >>= 1)
            se += __shfl_xor_sync(0xffffffffu, se, off);
        float pw = p / se;

        int k = 0;
        for (; k + 4 <= deg; k += 4) {
            int jk[4]; float pk[4];
#pragma unroll
            for (int u = 0; u < 4; u++) {
                jk[u] = __shfl_sync(0xffffffffu, jreg, k + u);
                pk[u] = __shfl_sync(0xffffffffu, pw, k + u);
            }
            uint2 v[4];
#pragma unroll
            for (int u = 0; u < 4; u++) v[u] = whb[(size_t)jk[u] * 32 + lane];
#pragma unroll
            for (int u = 0; u < 4; u++) {
                float2 f0 = __half22float2(*(__half2*)&v[u].x);
                float2 f1 = __half22float2(*(__half2*)&v[u].y);
                a0 += pk[u] * f0.x; a1 += pk[u] * f0.y;
                a2 += pk[u] * f1.x; a3 += pk[u] * f1.y;
            }
        }
        for (; k < deg; k++) {
            int jk = __shfl_sync(0xffffffffu, jreg, k);
            float pk = __shfl_sync(0xffffffffu, pw, k);
            uint2 v = whb[(size_t)jk * 32 + lane];
            float2 f0 = __half22float2(*(__half2*)&v.x);
            float2 f1 = __half22float2(*(__half2*)&v.y);
            a0 += pk * f0.x; a1 += pk * f0.y; a2 += pk * f1.x; a3 += pk * f1.y;
        }
    } else {
        // exact smem fallback (rare)
        float mx = NEG_BIG;
        for (int t = lane; t < deg; t += 32) {
            int j = g_cols[i * MAXDEG + t];
            sh_j[w][t] = j;
            float e = si + g_dT[j * 4 + b];
            e = e > 0.f ? e : 0.01f * e;
            sh_e[w][t] = e;
            mx = fmaxf(mx, e);
        }
#pragma unroll
        for (int off = 16; off > 0; off >>= 1)
            mx = fmaxf(mx, __shfl_xor_sync(0xffffffffu, mx, off));
        __syncwarp();
        float se = 0.f;
        for (int t = lane; t < deg; t += 32) {
            float p = __expf(sh_e[w][t] - mx);
            sh_e[w][t] = p;
            se += p;
        }
#pragma unroll
        for (int off = 16; off > 0; off >>= 1)
            se += __shfl_xor_sync(0xffffffffu, se, off);
        float iv = 1.f / se;
        __syncwarp();
        for (int k = 0; k < deg; k++) {
            float pk = sh_e[w][k] * iv;
            uint2 v = whb[(size_t)sh_j[w][k] * 32 + lane];
            float2 f0 = __half22float2(*(__half2*)&v.x);
            float2 f1 = __half22float2(*(__half2*)&v.y);
            a0 += pk * f0.x; a1 += pk * f0.y; a2 += pk * f1.x; a3 += pk * f1.y;
        }
    }

    uint2 o;
    o.x = pack_half(a0, a1);
    o.y = pack_half(a2, a3);
    ((uint2*)&g_outh[((size_t)b * N_ + i) * DOUT_])[lane] = o;
}

// ==== final: y = relu(adj @ out), warp per (row, single graph) =============
__global__ __launch_bounds__(256) void final_kernel(float* __restrict__ y) {
    __shared__ int sh_j[8][MAXDEG];     // fallback only
    int lane = threadIdx.x & 31;
    int w = threadIdx.x >> 5;
    int rl = w >> 2, b = w & 3;
    int i = blockIdx.x * 2 + rl;
    int deg = g_deg[i];

    const uint2* oub = (const uint2*)g_outh + (size_t)b * N_ * 32;
    float a0 = 0.f, a1 = 0.f, a2 = 0.f, a3 = 0.f;

    if (deg <= 32) {
        int jreg = lane < deg ? g_cols[i * MAXDEG + lane] : 0;
        int k = 0;
        for (; k + 4 <= deg; k += 4) {
            int jk[4];
#pragma unroll
            for (int u = 0; u < 4; u++) jk[u] = __shfl_sync(0xffffffffu, jreg, k + u);
            uint2 v[4];
#pragma unroll
            for (int u = 0; u < 4; u++) v[u] = oub[(size_t)jk[u] * 32 + lane];
#pragma unroll
            for (int u = 0; u < 4; u++) {
                float2 f0 = __half22float2(*(__half2*)&v[u].x);
                float2 f1 = __half22float2(*(__half2*)&v[u].y);
                a0 += f0.x; a1 += f0.y; a2 += f1.x; a3 += f1.y;
            }
        }
        for (; k < deg; k++) {
            int jk = __shfl_sync(0xffffffffu, jreg, k);
            uint2 v = oub[(size_t)jk * 32 + lane];
            float2 f0 = __half22float2(*(__half2*)&v.x);
            float2 f1 = __half22float2(*(__half2*)&v.y);
            a0 += f0.x; a1 += f0.y; a2 += f1.x; a3 += f1.y;
        }
    } else {
        for (int t = lane; t < deg; t += 32) sh_j[w][t] = g_cols[i * MAXDEG + t];
        __syncwarp();
        for (int k = 0; k < deg; k++) {
            uint2 v = oub[(size_t)sh_j[w][k] * 32 + lane];
            float2 f0 = __half22float2(*(__half2*)&v.x);
            float2 f1 = __half22float2(*(__half2*)&v.y);
            a0 += f0.x; a1 += f0.y; a2 += f1.x; a3 += f1.y;
        }
    }
    float4 r = make_float4(fmaxf(a0, 0.f), fmaxf(a1, 0.f),
                           fmaxf(a2, 0.f), fmaxf(a3, 0.f));
    ((float4*)&y[((size_t)b * N_ + i) * DOUT_])[lane] = r;
}

// ---------------- launch ----------------
extern "C" void kernel_launch(void* const* d_in, const int* in_sizes, int n_in,
                              void* d_out, int out_size) {
    const float* x   = (const float*)d_in[0];  // (B, N, DIN)
    const float* adj = (const float*)d_in[1];  // (N, N)
    const float* wts = (const float*)d_in[2];  // (DIN, DOUT)
    const float* a   = (const float*)d_in[3];  // (2*DOUT, 1)
    float* y = (float*)d_out;

    static cudaStream_t s2;
    static cudaEvent_t evA, evC;
    static int inited = 0;
    if (!inited) {
        cudaFuncSetAttribute(gemm_hmma_kernel,
                             cudaFuncAttributeMaxDynamicSharedMemorySize, SMEM_TOTAL);
        cudaStreamCreateWithFlags(&s2, cudaStreamNonBlocking);
        cudaEventCreateWithFlags(&evA, cudaEventDisableTiming);
        cudaEventCreateWithFlags(&evC, cudaEventDisableTiming);
        inited = 1;
    }
    cudaStream_t s0 = 0;

    // fork: csr on s2 overlaps convW+GEMM on s0; join before attn
    cudaEventRecord(evA, s0);
    cudaStreamWaitEvent(s2, evA, 0);
    csr_build_kernel<<<N_ / 8, 256, 0, s2>>>(adj);
    cudaEventRecord(evC, s2);

    convw_kernel<<<DIN_ * DOUT_ / 1024, 256, 0, s0>>>(wts);
    gemm_hmma_kernel<<<(B_ * N_) / 64, 256, SMEM_TOTAL, s0>>>(x, a);
    cudaStreamWaitEvent(s0, evC, 0);

    attn_kernel<<<N_ / 2, 256, 0, s0>>>();
    final_kernel<<<N_ / 2, 256, 0, s0>>>(y);
}

// round 16
// speedup vs baseline: 1.0442x; 1.0043x over previous
#include <cuda_runtime.h>
#include <cuda_bf16.h>
#include <cuda_fp16.h>
#include <math.h>
#include <stdint.h>

#define B_    4
#define N_    4096
#define DIN_  512
#define DOUT_ 128
#define MAXDEG 128
#define NEG_BIG -1e30f

// ---------------- scratch (static device memory; no allocs) ----------------
__device__ __half g_whh[B_ * N_ * DOUT_];   // x @ W (fp16)   4 MB
__device__ __half g_outh[B_ * N_ * DOUT_];  // att @ wh       4 MB
__device__ float g_sT[N_ * 4];              // s transposed [i][b]
__device__ float g_dT[N_ * 4];              // d transposed [i][b]
__device__ float g_csPart[256 * DOUT_];     // per-CTA colsum partials
__device__ int   g_cols[N_ * MAXDEG];
__device__ int   g_deg[N_];

// ============================ helpers =======================================
__device__ __forceinline__ uint32_t smem_u32(const void* p) {
    uint32_t a;
    asm("{ .reg .u64 t; cvta.to.shared.u64 t, %1; cvt.u32.u64 %0, t; }" : "=r"(a) : "l"(p));
    return a;
}
__device__ __forceinline__ void ldm_x4(uint32_t* f, uint32_t addr) {
    asm volatile("ldmatrix.sync.aligned.m8n8.x4.shared.b16 {%0,%1,%2,%3}, [%4];"
                 : "=r"(f[0]), "=r"(f[1]), "=r"(f[2]), "=r"(f[3]) : "r"(addr));
}
__device__ __forceinline__ void ldm_x4t(uint32_t* f, uint32_t addr) {
    asm volatile("ldmatrix.sync.aligned.m8n8.x4.trans.shared.b16 {%0,%1,%2,%3}, [%4];"
                 : "=r"(f[0]), "=r"(f[1]), "=r"(f[2]), "=r"(f[3]) : "r"(addr));
}
__device__ __forceinline__ void mma_f16(float* c, const uint32_t* a, const uint32_t* b) {
    asm volatile(
        "mma.sync.aligned.m16n8k16.row.col.f32.f16.f16.f32 "
        "{%0,%1,%2,%3}, {%4,%5,%6,%7}, {%8,%9}, {%0,%1,%2,%3};"
        : "+f"(c[0]), "+f"(c[1]), "+f"(c[2]), "+f"(c[3])
        : "r"(a[0]), "r"(a[1]), "r"(a[2]), "r"(a[3]), "r"(b[0]), "r"(b[1]));
}
__device__ __forceinline__ uint32_t pack_half(float x, float y) {
    __half2 h = __floats2half2_rn(x, y);
    return *(uint32_t*)&h;
}
__device__ __forceinline__ void acc8(float* a, uint4 v, float p) {
    float2 f;
    f = __half22float2(*(__half2*)&v.x); a[0] += p * f.x; a[1] += p * f.y;
    f = __half22float2(*(__half2*)&v.y); a[2] += p * f.x; a[3] += p * f.y;
    f = __half22float2(*(__half2*)&v.z); a[4] += p * f.x; a[5] += p * f.y;
    f = __half22float2(*(__half2*)&v.w); a[6] += p * f.x; a[7] += p * f.y;
}
__device__ __forceinline__ void add8(float* a, uint4 v) {
    float2 f;
    f = __half22float2(*(__half2*)&v.x); a[0] += f.x; a[1] += f.y;
    f = __half22float2(*(__half2*)&v.y); a[2] += f.x; a[3] += f.y;
    f = __half22float2(*(__half2*)&v.z); a[4] += f.x; a[5] += f.y;
    f = __half22float2(*(__half2*)&v.w); a[6] += f.x; a[7] += f.y;
}

// =============== CSR build: warp/row, 4 loads in flight ====================
__global__ void csr_build_kernel(const float* __restrict__ adj) {
    int warp = (blockIdx.x * blockDim.x + threadIdx.x) >> 5;
    int lane = threadIdx.x & 31;
    if (warp >= N_) return;
    const float4* row = (const float4*)(adj + (size_t)warp * N_);
    int cnt = 0;
    for (int base = 0; base < N_; base += 512) {
        float4 v0 = row[(base >> 2) + lane];
        float4 v1 = row[(base >> 2) + 32 + lane];
        float4 v2 = row[(base >> 2) + 64 + lane];
        float4 v3 = row[(base >> 2) + 96 + lane];
        float c16[16] = {v0.x, v0.y, v0.z, v0.w, v1.x, v1.y, v1.z, v1.w,
                         v2.x, v2.y, v2.z, v2.w, v3.x, v3.y, v3.z, v3.w};
#pragma unroll
        for (int h = 0; h < 4; h++) {
#pragma unroll
            for (int c = 0; c < 4; c++) {
                float f = c16[h * 4 + c];
                unsigned m = __ballot_sync(0xffffffffu, f > 0.0f);
                if (f > 0.0f) {
                    int pos = cnt + __popc(m & ((1u << lane) - 1u));
                    if (pos < MAXDEG)
                        g_cols[warp * MAXDEG + pos] = base + h * 128 + lane * 4 + c;
                }
                cnt += __popc(m);
            }
        }
    }
    if (lane == 0) g_deg[warp] = cnt < MAXDEG ? cnt : MAXDEG;
}

// ===== HMMA GEMM (fp16, inline W convert): wh = x @ W ======================
#define KC 32
#define NCH (DIN_ / KC)          // 16
#define A_STG 8192               // 64 rows * 128B
#define B_STG 8192               // 32 k * 128 n * 2B
#define SM_A 0
#define SM_B (2 * A_STG)
#define SM_SD (SM_B + 2 * B_STG)          // s_sm[64], d_sm[64]
#define SM_AV (SM_SD + 512)               // a_s[128], a_d[128]
#define SM_CS (SM_AV + 1024)              // cs[128]
#define SMEM_TOTAL (SM_CS + 512)

__device__ __forceinline__ uint32_t a_off(int r, int gran) {
    return (uint32_t)(r * 128 + ((gran ^ (r & 7)) << 4));
}
__device__ __forceinline__ uint32_t b_off2(int k, int gran) {
    return (uint32_t)(k * 256 + ((gran ^ (k & 7)) << 4));
}

__global__ __launch_bounds__(256, 2) void gemm_hmma_kernel(
    const float* __restrict__ x, const float* __restrict__ W,
    const float* __restrict__ a) {
    extern __shared__ char smem[];
    const uint32_t sb = smem_u32(smem);
    const int tid = threadIdx.x;
    const int wid = tid >> 5, lane = tid & 31;
    const int wm = wid >> 1, wn = wid & 1;     // warp tile: 16 rows x 64 cols
    const int tig = lane & 3, grp = lane >> 2;

    float* s_sm = (float*)(smem + SM_SD);
    float* d_sm = (float*)(smem + SM_SD + 256);
    float* a_s  = (float*)(smem + SM_AV);
    float* a_d  = (float*)(smem + SM_AV + 512);
    float* cs   = (float*)(smem + SM_CS);
    if (tid < 128) {
        cs[tid] = 0.0f;
        a_s[tid] = a[tid]; a_d[tid] = a[DOUT_ + tid];
    }
    if (tid < 64) { s_sm[tid] = 0.0f; d_sm[tid] = 0.0f; }

    const int R0 = blockIdx.x * 64;
    const int arow = tid >> 2, akoff = (tid & 3) * 8;
    const float* pA = x + (size_t)(R0 + arow) * DIN_ + akoff;
    const int bk = tid >> 3, bgr = (tid & 7) * 2;
    const float4* W4 = (const float4*)W;
    const int wbase = bk * 32 + bgr * 2;    // float4 index within chunk row

    float acc[8][4];
#pragma unroll
    for (int j = 0; j < 8; j++)
#pragma unroll
        for (int q = 0; q < 4; q++) acc[j][q] = 0.0f;

    float4 ra[2];
    float4 rbw[4];
    ra[0] = *(const float4*)(pA);
    ra[1] = *(const float4*)(pA + 4);
#pragma unroll
    for (int q = 0; q < 4; q++) rbw[q] = W4[wbase + q];

    for (int c = 0; c < NCH; c++) {
        const int buf = c & 1;
        char* Abuf = smem + SM_A + buf * A_STG;
        char* Bbuf = smem + SM_B + buf * B_STG;

        {
            const float* fa = (const float*)ra;
#pragma unroll
            for (int p = 0; p < 4; p++) {
                uint32_t hv = pack_half(fa[2 * p], fa[2 * p + 1]);
                int kl = akoff + 2 * p;
                int gr = kl >> 3, wi = (kl & 7) * 2;
                *(uint32_t*)(Abuf + a_off(arow, gr) + wi) = hv;
            }
            uint4 u0, u1;
            u0.x = pack_half(rbw[0].x, rbw[0].y); u0.y = pack_half(rbw[0].z, rbw[0].w);
            u0.z = pack_half(rbw[1].x, rbw[1].y); u0.w = pack_half(rbw[1].z, rbw[1].w);
            u1.x = pack_half(rbw[2].x, rbw[2].y); u1.y = pack_half(rbw[2].z, rbw[2].w);
            u1.z = pack_half(rbw[3].x, rbw[3].y); u1.w = pack_half(rbw[3].z, rbw[3].w);
            *(uint4*)(Bbuf + b_off2(bk, bgr))     = u0;
            *(uint4*)(Bbuf + b_off2(bk, bgr + 1)) = u1;
        }
        __syncthreads();

        if (c + 1 < NCH) {
            const float* qA = pA + (c + 1) * KC;
            ra[0] = *(const float4*)(qA);
            ra[1] = *(const float4*)(qA + 4);
            int gi = (c + 1) * 1024 + wbase;   // chunk = 32 rows * 32 f4 = 1024 f4
#pragma unroll
            for (int q = 0; q < 4; q++) rbw[q] = W4[gi + q];
        }

        const uint32_t Abase = sb + SM_A + buf * A_STG;
        const uint32_t Bbase = sb + SM_B + buf * B_STG;
#pragma unroll
        for (int ks = 0; ks < 2; ks++) {
            uint32_t ahi[4];
            {
                int R = wm * 16 + (lane & 15);
                int gh = 2 * ks + (lane >> 4);
                ldm_x4(ahi, Abase + a_off(R, gh));
            }
            int kk = 16 * ks + (lane & 15);
#pragma unroll
            for (int ntp = 0; ntp < 4; ntp++) {
                int gn = wn * 8 + ntp * 2 + (lane >> 4);
                uint32_t bb[4];
                ldm_x4t(bb, Bbase + b_off2(kk, gn));
                mma_f16(acc[ntp * 2],     ahi, bb);
                mma_f16(acc[ntp * 2 + 1], ahi, bb + 2);
            }
        }
        __syncthreads();
    }

    // ---- epilogue: store wh (fp16), fused s/d dots + column sums ----
    float sacc[2] = {0, 0}, dacc[2] = {0, 0};
    int rbase = R0 + wm * 16 + grp;
#pragma unroll
    for (int nt = 0; nt < 8; nt++) {
        int col = wn * 64 + nt * 8 + tig * 2;
        float* cf = acc[nt];
        sacc[0] += cf[0] * a_s[col] + cf[1] * a_s[col + 1];
        sacc[1] += cf[2] * a_s[col] + cf[3] * a_s[col + 1];
        dacc[0] += cf[0] * a_d[col] + cf[1] * a_d[col + 1];
        dacc[1] += cf[2] * a_d[col] + cf[3] * a_d[col + 1];
        *(__half2*)&g_whh[(size_t)rbase * DOUT_ + col] =
            __float22half2_rn(make_float2(cf[0], cf[1]));
        *(__half2*)&g_whh[(size_t)(rbase + 8) * DOUT_ + col] =
            __float22half2_rn(make_float2(cf[2], cf[3]));

        float v0 = cf[0] + cf[2];
        float v1 = cf[1] + cf[3];
#pragma unroll
        for (int off = 16; off >= 4; off >>= 1) {
            v0 += __shfl_down_sync(0xffffffffu, v0, off);
            v1 += __shfl_down_sync(0xffffffffu, v1, off);
        }
        if (lane < 4) {
            atomicAdd(&cs[col], v0);
            atomicAdd(&cs[col + 1], v1);
        }
    }
#pragma unroll
    for (int h = 0; h < 2; h++) {
        sacc[h] += __shfl_xor_sync(0xffffffffu, sacc[h], 1);
        sacc[h] += __shfl_xor_sync(0xffffffffu, sacc[h], 2);
        dacc[h] += __shfl_xor_sync(0xffffffffu, dacc[h], 1);
        dacc[h] += __shfl_xor_sync(0xffffffffu, dacc[h], 2);
    }
    if (tig == 0) {
        int r = wm * 16 + grp;
        atomicAdd(&s_sm[r], sacc[0]);
        atomicAdd(&s_sm[r + 8], sacc[1]);
        atomicAdd(&d_sm[r], dacc[0]);
        atomicAdd(&d_sm[r + 8], dacc[1]);
    }
    __syncthreads();
    if (tid < 64) {
        int b = R0 / N_;
        int il = (R0 % N_) + tid;
        g_sT[il * 4 + b] = s_sm[tid];
        g_dT[il * 4 + b] = d_sm[tid];
    }
    if (tid < 128) g_csPart[blockIdx.x * DOUT_ + tid] = cs[tid];
}

// ==== attention: warp per (row, graph-pair); half-warp uint4 gather ========
__global__ __launch_bounds__(256) void attn_kernel() {
    __shared__ float sh_e[8][MAXDEG][2];
    __shared__ int   sh_j[8][MAXDEG];
    int lane = threadIdx.x & 31;
    int w = threadIdx.x >> 5;
    int rl = w >> 1, pr = w & 1;
    int i = blockIdx.x * 4 + rl;
    int deg = g_deg[i];
    int b0 = 2 * pr;
    int half = lane >> 4, sl = lane & 15;
    int bg = b0 + half;                         // this lane's graph

    char* outp = (char*)g_outh + ((size_t)bg * N_ + i) * 256 + sl * 16;

    if (deg == 0) {
        float inv = 1.0f / (float)N_;
        float4 m0 = make_float4(0, 0, 0, 0), m1 = make_float4(0, 0, 0, 0);
        for (int c = 0; c < 64; c++) {
            const float4* ps = (const float4*)&g_csPart[(bg * 64 + c) * DOUT_];
            float4 u = ps[sl * 2], v = ps[sl * 2 + 1];
            m0.x += u.x; m0.y += u.y; m0.z += u.z; m0.w += u.w;
            m1.x += v.x; m1.y += v.y; m1.z += v.z; m1.w += v.w;
        }
        uint4 o;
        o.x = pack_half(m0.x * inv, m0.y * inv);
        o.y = pack_half(m0.z * inv, m0.w * inv);
        o.z = pack_half(m1.x * inv, m1.y * inv);
        o.w = pack_half(m1.z * inv, m1.w * inv);
        *(uint4*)outp = o;
        return;
    }

    float2 s2 = *(const float2*)&g_sT[i * 4 + b0];
    float mx0 = NEG_BIG, mx1 = NEG_BIG;
    for (int t = lane; t < deg; t += 32) {
        int j = g_cols[i * MAXDEG + t];
        sh_j[w][t] = j;
        float2 d2 = *(const float2*)&g_dT[j * 4 + b0];
        float e0 = s2.x + d2.x; e0 = e0 > 0.f ? e0 : 0.01f * e0;
        float e1 = s2.y + d2.y; e1 = e1 > 0.f ? e1 : 0.01f * e1;
        *(float2*)sh_e[w][t] = make_float2(e0, e1);
        mx0 = fmaxf(mx0, e0); mx1 = fmaxf(mx1, e1);
    }
#pragma unroll
    for (int off = 16; off > 0; off >>= 1) {
        mx0 = fmaxf(mx0, __shfl_xor_sync(0xffffffffu, mx0, off));
        mx1 = fmaxf(mx1, __shfl_xor_sync(0xffffffffu, mx1, off));
    }
    __syncwarp();

    float se0 = 0.f, se1 = 0.f;
    for (int t = lane; t < deg; t += 32) {
        float2 e = *(float2*)sh_e[w][t];
        float p0 = __expf(e.x - mx0), p1 = __expf(e.y - mx1);
        *(float2*)sh_e[w][t] = make_float2(p0, p1);
        se0 += p0; se1 += p1;
    }
#pragma unroll
    for (int off = 16; off > 0; off >>= 1) {
        se0 += __shfl_xor_sync(0xffffffffu, se0, off);
        se1 += __shfl_xor_sync(0xffffffffu, se1, off);
    }
    float ivsel = half ? (1.f / se1) : (1.f / se0);
    __syncwarp();

    const char* whbase = (const char*)g_whh + (size_t)bg * N_ * 256 + sl * 16;
    float acl[8];
#pragma unroll
    for (int q = 0; q < 8; q++) acl[q] = 0.f;

    int k = 0;
    for (; k + 2 <= deg; k += 2) {
        int j0 = sh_j[w][k], j1 = sh_j[w][k + 1];
        float2 pe0 = *(float2*)sh_e[w][k];
        float2 pe1 = *(float2*)sh_e[w][k + 1];
        uint4 v0 = *(const uint4*)(whbase + (size_t)j0 * 256);
        uint4 v1 = *(const uint4*)(whbase + (size_t)j1 * 256);
        float pw0 = (half ? pe0.y : pe0.x) * ivsel;
        float pw1 = (half ? pe1.y : pe1.x) * ivsel;
        acc8(acl, v0, pw0);
        acc8(acl, v1, pw1);
    }
    if (k < deg) {
        int j0 = sh_j[w][k];
        float2 pe0 = *(float2*)sh_e[w][k];
        uint4 v0 = *(const uint4*)(whbase + (size_t)j0 * 256);
        float pw0 = (half ? pe0.y : pe0.x) * ivsel;
        acc8(acl, v0, pw0);
    }
    uint4 o;
    o.x = pack_half(acl[0], acl[1]);
    o.y = pack_half(acl[2], acl[3]);
    o.z = pack_half(acl[4], acl[5]);
    o.w = pack_half(acl[6], acl[7]);
    *(uint4*)outp = o;
}

// ==== final: y = relu(adj @ out); half-warp uint4 gather ====================
__global__ __launch_bounds__(256) void final_kernel(float* __restrict__ y) {
    __shared__ int sh_j[8][MAXDEG];
    int lane = threadIdx.x & 31;
    int w = threadIdx.x >> 5;
    int rl = w >> 1, pr = w & 1;
    int i = blockIdx.x * 4 + rl;
    int deg = g_deg[i];
    int b0 = 2 * pr;
    int half = lane >> 4, sl = lane & 15;
    int bg = b0 + half;

    for (int t = lane; t < deg; t += 32) sh_j[w][t] = g_cols[i * MAXDEG + t];
    __syncwarp();

    const char* obase = (const char*)g_outh + (size_t)bg * N_ * 256 + sl * 16;
    float acl[8];
#pragma unroll
    for (int q = 0; q < 8; q++) acl[q] = 0.f;

    int k = 0;
    for (; k + 2 <= deg; k += 2) {
        int j0 = sh_j[w][k], j1 = sh_j[w][k + 1];
        uint4 v0 = *(const uint4*)(obase + (size_t)j0 * 256);
        uint4 v1 = *(const uint4*)(obase + (size_t)j1 * 256);
        add8(acl, v0);
        add8(acl, v1);
    }
    if (k < deg) {
        uint4 v0 = *(const uint4*)(obase + (size_t)sh_j[w][k] * 256);
        add8(acl, v0);
    }
    float4 r0 = make_float4(fmaxf(acl[0], 0.f), fmaxf(acl[1], 0.f),
                            fmaxf(acl[2], 0.f), fmaxf(acl[3], 0.f));
    float4 r1 = make_float4(fmaxf(acl[4], 0.f), fmaxf(acl[5], 0.f),
                            fmaxf(acl[6], 0.f), fmaxf(acl[7], 0.f));
    float4* yp = (float4*)(y + ((size_t)bg * N_ + i) * DOUT_ + sl * 8);
    yp[0] = r0;
    yp[1] = r1;
}

// ---------------- launch ----------------
extern "C" void kernel_launch(void* const* d_in, const int* in_sizes, int n_in,
                              void* d_out, int out_size) {
    const float* x   = (const float*)d_in[0];  // (B, N, DIN)
    const float* adj = (const float*)d_in[1];  // (N, N)
    const float* wts = (const float*)d_in[2];  // (DIN, DOUT)
    const float* a   = (const float*)d_in[3];  // (2*DOUT, 1)
    float* y = (float*)d_out;

    static cudaStream_t s2;
    static cudaEvent_t evA, evC;
    static int inited = 0;
    if (!inited) {
        cudaFuncSetAttribute(gemm_hmma_kernel,
                             cudaFuncAttributeMaxDynamicSharedMemorySize, SMEM_TOTAL);
        cudaStreamCreateWithFlags(&s2, cudaStreamNonBlocking);
        cudaEventCreateWithFlags(&evA, cudaEventDisableTiming);
        cudaEventCreateWithFlags(&evC, cudaEventDisableTiming);
        inited = 1;
    }
    cudaStream_t s0 = 0;

    // fork: csr on s2 overlaps GEMM on s0; join before attn
    cudaEventRecord(evA, s0);
    cudaStreamWaitEvent(s2, evA, 0);
    csr_build_kernel<<<N_ / 8, 256, 0, s2>>>(adj);
    cudaEventRecord(evC, s2);

    gemm_hmma_kernel<<<(B_ * N_) / 64, 256, SMEM_TOTAL, s0>>>(x, wts, a);
    cudaStreamWaitEvent(s0, evC, 0);

    attn_kernel<<<N_ / 4, 256, 0, s0>>>();
    final_kernel<<<N_ / 4, 256, 0, s0>>>(y);
}